// round 16
// baseline (speedup 1.0000x reference)
#include <cuda_runtime.h>
#include <cuda_bf16.h>
#include <cstdint>
#include <math.h>
#include <float.h>

#define NN 20000
#define EE 320000
#define RR 8
#define NPAD 20096   // 157 * 128

// ---------------- scratch (device globals) ----------------
__device__ float g_dis[NN];
__device__ float g_h1[NN * 32];
__device__ float g_c1[NN * 32];
__device__ float g_h2[NN * 128];
__device__ __align__(16) float g_x0[NN * 256];
__device__ __align__(16) float g_hmid[NN * 256];
__device__ __align__(16) float g_outp[NN * 256];
__device__ __align__(16) float g_T[NN * 256];
__device__ float g_qkn[NN * 64];
__device__ float g_m[NN * 4];
__device__ float g_den[NN * 4];
__device__ float g_wcat[256 * 64];
__device__ float g_a1s[EE * 4];
__device__ float g_a2s[EE * 4];

// bf16-split staging
__device__ __align__(16) __nv_bfloat16 g_Xhi[(long)NPAD * 256];
__device__ __align__(16) __nv_bfloat16 g_Xlo[(long)NPAD * 256];
__device__ __align__(16) __nv_bfloat16 g_Hhi[(long)NPAD * 256];
__device__ __align__(16) __nv_bfloat16 g_Hlo[(long)NPAD * 256];
__device__ __align__(16) __nv_bfloat16 g_Bhi[9L * 65536];   // slots 0-7 rel, 8 lin (Wt[n][k])
__device__ __align__(16) __nv_bfloat16 g_Blo[9L * 65536];

// CSR infrastructure
__device__ int g_degi[NN];
__device__ int g_offD[NN + 1];
__device__ int g_posD[NN];
__device__ int g_eordD[EE];
__device__ int g_cnt2[RR * NN];
__device__ int g_off2[RR * NN + 1];
__device__ int g_pos2[RR * NN];
__device__ int g_eord2[EE];
__device__ int g_bsum[512];

#define SZ_256  ((long)NN * 256)
#define SZ_A    ((long)EE * 4)
#define SZ_OUT  (SZ_256 + 2 * SZ_A)

// ---------------- helpers ----------------
__device__ __forceinline__ float lrelu(float x, float s) { return x > 0.f ? x : s * x; }

__device__ __forceinline__ int clampi(int v, int lo, int hi) {
    return v < lo ? lo : (v > hi ? hi : v);
}

__device__ __forceinline__ void atomicMaxF(float* addr, float v) {
    if (v >= 0.f) atomicMax((int*)addr, __float_as_int(v));
    else          atomicMin((unsigned int*)addr, __float_as_uint(v));
}

// ---------------- CSR build ----------------
__global__ void k_zero_hist() {
    int i = blockIdx.x * blockDim.x + threadIdx.x;
    if (i < NN) g_degi[i] = 0;
    if (i < RR * NN) g_cnt2[i] = 0;
}

__global__ void k_ehist(const int* __restrict__ dstp, const int* __restrict__ et) {
    int e = blockIdx.x * blockDim.x + threadIdx.x;
    if (e >= EE) return;
    int d = clampi(dstp[e], 0, NN - 1);
    int r = clampi(et[e], 0, RR - 1);
    atomicAdd(&g_degi[d], 1);
    atomicAdd(&g_cnt2[r * NN + d], 1);
}

// 3-phase multi-block exclusive scan.
__global__ void k_scanA(int which) {
    const int* cnt = which ? g_cnt2 : g_degi;
    int n = which ? RR * NN : NN;
    __shared__ int sh[1024];
    int t = threadIdx.x;
    int i = blockIdx.x * 1024 + t;
    sh[t] = (i < n) ? cnt[i] : 0;
    __syncthreads();
    for (int o = 512; o > 0; o >>= 1) {
        if (t < o) sh[t] += sh[t + o];
        __syncthreads();
    }
    if (t == 0) g_bsum[blockIdx.x] = sh[0];
}

__global__ void k_scanB(int nb) {
    __shared__ int sh[256];
    int t = threadIdx.x;
    int own = (t < nb) ? g_bsum[t] : 0;
    sh[t] = own;
    __syncthreads();
    for (int o = 1; o < 256; o <<= 1) {
        int v = (t >= o) ? sh[t - o] : 0;
        __syncthreads();
        sh[t] += v;
        __syncthreads();
    }
    if (t < nb) g_bsum[t] = sh[t] - own;   // exclusive
}

__global__ void k_scanC(int which) {
    const int* cnt = which ? g_cnt2 : g_degi;
    int* off       = which ? g_off2 : g_offD;
    int n = which ? RR * NN : NN;
    __shared__ int sh[1024];
    int t = threadIdx.x;
    int i = blockIdx.x * 1024 + t;
    int own = (i < n) ? cnt[i] : 0;
    sh[t] = own;
    __syncthreads();
    for (int o = 1; o < 1024; o <<= 1) {
        int v = (t >= o) ? sh[t - o] : 0;
        __syncthreads();
        sh[t] += v;
        __syncthreads();
    }
    int base = g_bsum[blockIdx.x];
    if (i < n) {
        off[i] = base + sh[t] - own;
        if (i == n - 1) off[n] = base + sh[t];
    }
}

__global__ void k_pos_copy() {
    int i = blockIdx.x * blockDim.x + threadIdx.x;
    if (i < NN) g_posD[i] = g_offD[i];
    if (i < RR * NN) g_pos2[i] = g_off2[i];
}

__global__ void k_escat(const int* __restrict__ dstp, const int* __restrict__ et) {
    int e = blockIdx.x * blockDim.x + threadIdx.x;
    if (e >= EE) return;
    int d = clampi(dstp[e], 0, NN - 1);
    int r = clampi(et[e], 0, RR - 1);
    int sD = atomicAdd(&g_posD[d], 1);
    if (sD >= 0 && sD < EE) g_eordD[sD] = e;
    int s2 = atomicAdd(&g_pos2[r * NN + d], 1);
    if (s2 >= 0 && s2 < EE) g_eord2[s2] = e;
}

__global__ void k_dis() {
    int i = blockIdx.x * blockDim.x + threadIdx.x;
    if (i < NN) g_dis[i] = rsqrtf((float)g_degi[i] + 1.0f);
}

// ---------------- GCN ----------------
__global__ void k_h1(const float* __restrict__ x, const float* __restrict__ W) {
    int i = blockIdx.x * blockDim.x + threadIdx.x;
    if (i >= NN * 32) return;
    int n = i >> 5, j = i & 31;
    float c0 = x[n * 4 + 0], c1 = x[n * 4 + 1], c2 = x[n * 4 + 2], c3 = x[n * 4 + 3];
    g_h1[i] = c0 * W[j] + c1 * W[32 + j] + c2 * W[64 + j] + c3 * W[96 + j];
}

__global__ void k_gcn_init32(const float* __restrict__ b) {
    int i = blockIdx.x * blockDim.x + threadIdx.x;
    if (i >= NN * 32) return;
    int n = i >> 5, j = i & 31;
    float d = g_dis[n];
    g_c1[i] = b[j] + d * d * g_h1[i];
}

__global__ void k_gcn_csr1(const int* __restrict__ src) {
    int wid = (blockIdx.x * blockDim.x + threadIdx.x) >> 5;
    int lane = threadIdx.x & 31;
    if (wid >= NN) return;
    int a = g_offD[wid], b = g_offD[wid + 1];
    float acc = 0.f;
    for (int i = a; i < b; i++) {
        int e = g_eordD[i];
        int s = clampi(src[e], 0, NN - 1);
        acc = fmaf(g_dis[s], g_h1[(long)s * 32 + lane], acc);
    }
    g_c1[(long)wid * 32 + lane] += g_dis[wid] * acc;
}

__global__ void k_leaky_c1(float s) {
    int i = blockIdx.x * blockDim.x + threadIdx.x;
    if (i >= NN * 32) return;
    g_c1[i] = lrelu(g_c1[i], s);
}

__global__ void k_h2(const float* __restrict__ W2) {
    __shared__ float cs[32];
    int n = blockIdx.x, t = threadIdx.x;
    if (t < 32) cs[t] = g_c1[(long)n * 32 + t];
    __syncthreads();
    float acc = 0.f;
#pragma unroll
    for (int k = 0; k < 32; k++) acc = fmaf(cs[k], W2[k * 128 + t], acc);
    g_h2[(long)n * 128 + t] = acc;
}

__global__ void k_build_x0(const float* __restrict__ kg, const float* __restrict__ b2) {
    int i = blockIdx.x * blockDim.x + threadIdx.x;
    if (i >= NN * 256) return;
    int n = i >> 8, c = i & 255;
    if (c < 128) g_x0[i] = kg[(long)n * 128 + c];
    else {
        float d = g_dis[n];
        g_x0[i] = b2[c - 128] + d * d * g_h2[(long)n * 128 + (c - 128)];
    }
}

__global__ void k_gcn_csr2(const int* __restrict__ src) {
    int d = blockIdx.x, t = threadIdx.x;
    int a = g_offD[d], b = g_offD[d + 1];
    float acc = 0.f;
    for (int i = a; i < b; i++) {
        int e = g_eordD[i];
        int s = clampi(src[e], 0, NN - 1);
        acc = fmaf(g_dis[s], g_h2[(long)s * 128 + t], acc);
    }
    g_x0[(long)d * 256 + 128 + t] += g_dis[d] * acc;
}

// ---------------- bf16-split conversions ----------------
__global__ void k_convA(int sel) {
    long i = (long)blockIdx.x * blockDim.x + threadIdx.x;
    if (i >= (long)NPAD * 256) return;
    float v = 0.f;
    if (i < SZ_256) v = sel ? g_hmid[i] : g_x0[i];
    __nv_bfloat16 h = __float2bfloat16(v);
    __nv_bfloat16 l = __float2bfloat16(v - __bfloat162float(h));
    if (sel) { g_Hhi[i] = h; g_Hlo[i] = l; }
    else     { g_Xhi[i] = h; g_Xlo[i] = l; }
}

// W[r][k][n] fp32 -> slot (slot0+r): Wt[n][k] bf16 hi/lo (K-major per output col)
__global__ void k_convW(const float* __restrict__ W, int nrel, int slot0) {
    long i = (long)blockIdx.x * blockDim.x + threadIdx.x;
    if (i >= (long)nrel * 65536) return;
    int r = (int)(i >> 16);
    int rem = (int)(i & 65535);
    int n = rem >> 8, k = rem & 255;
    float v = W[(long)r * 65536 + (long)k * 256 + n];
    __nv_bfloat16 h = __float2bfloat16(v);
    __nv_bfloat16 l = __float2bfloat16(v - __bfloat162float(h));
    long o = (long)(slot0 + r) * 65536 + (long)n * 256 + k;
    g_Bhi[o] = h;
    g_Blo[o] = l;
}

// ---------------- HMMA GEMM: C[m, n0..n0+63] (+)= A @ B_slot ----------------
// mma.sync.aligned.m16n8k16.row.col.f32.bf16.bf16.f32 (portable, works on sm_103)
// 256 thr / 8 warps; warp w owns rows m0+w*16..+15; N-block 64; full K=256 in smem.
// D = Ah*Bh + Ah*Bl + Al*Bh, fp32 accum. Smem rows padded to 264 bf16 (132 words):
// fragment LDS bank = (4g + j) mod 32 -> conflict-free.
#define HW 132                 // words per smem row
#define OFF_AH 0
#define OFF_AL (128 * HW)
#define OFF_BH (256 * HW)
#define OFF_BL (256 * HW + 64 * HW)
#define HM_SMEM ((256 * HW + 128 * HW) * 4)   // 202752 bytes

__device__ __forceinline__ void hmma(float* c, uint32_t a0, uint32_t a1, uint32_t a2,
                                     uint32_t a3, uint32_t b0, uint32_t b1) {
    asm volatile(
        "mma.sync.aligned.m16n8k16.row.col.f32.bf16.bf16.f32 "
        "{%0,%1,%2,%3}, {%4,%5,%6,%7}, {%8,%9}, {%0,%1,%2,%3};"
        : "+f"(c[0]), "+f"(c[1]), "+f"(c[2]), "+f"(c[3])
        : "r"(a0), "r"(a1), "r"(a2), "r"(a3), "r"(b0), "r"(b1));
}

__global__ __launch_bounds__(256, 1) void k_hmma(int asel, int slot, int cmode, int accum) {
    extern __shared__ __align__(16) uint32_t sw[];
    int tid = threadIdx.x;
    int w = tid >> 5, lane = tid & 31;
    int g = lane >> 2, j = lane & 3;
    long m0 = (long)blockIdx.x * 128;
    long n0 = (long)blockIdx.y * 64;

    const __nv_bfloat16* Ah = asel ? g_Hhi : g_Xhi;
    const __nv_bfloat16* Al = asel ? g_Hlo : g_Xlo;
    const __nv_bfloat16* Bh = g_Bhi + (long)slot * 65536;
    const __nv_bfloat16* Bl = g_Blo + (long)slot * 65536;

    // stage A: 128 rows x 32 uint4 each (hi & lo). A arrays padded to NPAD: no guard.
    for (int i = tid; i < 4096; i += 256) {
        int row = i >> 5, q = i & 31;
        long srcb = (m0 + row) * 256 + q * 8;
        *(uint4*)(sw + OFF_AH + row * HW + q * 4) = *(const uint4*)(Ah + srcb);
        *(uint4*)(sw + OFF_AL + row * HW + q * 4) = *(const uint4*)(Al + srcb);
    }
    // stage B: 64 rows x 32 uint4 (hi & lo)
    for (int i = tid; i < 2048; i += 256) {
        int row = i >> 5, q = i & 31;
        long srcb = (n0 + row) * 256 + q * 8;
        *(uint4*)(sw + OFF_BH + row * HW + q * 4) = *(const uint4*)(Bh + srcb);
        *(uint4*)(sw + OFF_BL + row * HW + q * 4) = *(const uint4*)(Bl + srcb);
    }
    __syncthreads();

    float c[8][4];
#pragma unroll
    for (int nt = 0; nt < 8; nt++)
#pragma unroll
        for (int q = 0; q < 4; q++) c[nt][q] = 0.f;

    const uint32_t* aHbase = sw + OFF_AH + (w * 16 + g) * HW;
    const uint32_t* aLbase = sw + OFF_AL + (w * 16 + g) * HW;

    for (int kc = 0; kc < 16; kc++) {
        int kw = kc * 8 + j;
        uint32_t ah0 = aHbase[kw];
        uint32_t ah1 = aHbase[8 * HW + kw];
        uint32_t ah2 = aHbase[kw + 4];
        uint32_t ah3 = aHbase[8 * HW + kw + 4];
        uint32_t al0 = aLbase[kw];
        uint32_t al1 = aLbase[8 * HW + kw];
        uint32_t al2 = aLbase[kw + 4];
        uint32_t al3 = aLbase[8 * HW + kw + 4];
#pragma unroll
        for (int nt = 0; nt < 8; nt++) {
            const uint32_t* bH = sw + OFF_BH + (nt * 8 + g) * HW;
            const uint32_t* bL = sw + OFF_BL + (nt * 8 + g) * HW;
            uint32_t bh0 = bH[kw], bh1 = bH[kw + 4];
            uint32_t bl0 = bL[kw], bl1 = bL[kw + 4];
            hmma(c[nt], ah0, ah1, ah2, ah3, bh0, bh1);
            hmma(c[nt], ah0, ah1, ah2, ah3, bl0, bl1);
            hmma(c[nt], al0, al1, al2, al3, bh0, bh1);
        }
    }

    // epilogue: c0,c1 -> row m0+w*16+g, cols n0+nt*8+2j,+1 ; c2,c3 -> row +8
    float* C = (cmode == 0) ? g_T : g_outp;
    long r0 = m0 + w * 16 + g;
    long r1 = r0 + 8;
#pragma unroll
    for (int nt = 0; nt < 8; nt++) {
        long col = n0 + nt * 8 + 2 * j;
        if (r0 < NN) {
            float* p = C + r0 * 256 + col;
            if (accum) { p[0] += c[nt][0]; p[1] += c[nt][1]; }
            else       { p[0] = c[nt][0];  p[1] = c[nt][1]; }
        }
        if (r1 < NN) {
            float* p = C + r1 * 256 + col;
            if (accum) { p[0] += c[nt][2]; p[1] += c[nt][3]; }
            else       { p[0] = c[nt][2];  p[1] = c[nt][3]; }
        }
    }
}

// ---------------- attention (fp32 path) ----------------
__global__ void k_wcat(const float* __restrict__ W, const float* __restrict__ q,
                       const float* __restrict__ k) {
    int i = blockIdx.x, t = threadIdx.x;
    int c = t & 31, r = c >> 2, h = c & 3;
    const float* qk = (t >= 32) ? k : q;
    const float* wp = W + (long)r * 65536 + (long)i * 256;
    float acc = 0.f;
#pragma unroll 8
    for (int j = 0; j < 256; j++) acc = fmaf(wp[j], qk[j * 4 + h], acc);
    g_wcat[i * 64 + t] = acc;
}

__global__ void k_mmA(int amode) {
    __shared__ float xs[4][256];
    const float* A = (amode == 0) ? g_x0 : g_hmid;
    int t = threadIdx.x;
    long node0 = (long)blockIdx.x * 4;
    for (int i = t; i < 1024; i += 256) xs[i >> 8][i & 255] = A[node0 * 256 + i];
    __syncthreads();
    int l = t >> 6, c = t & 63;
    float acc = 0.f;
#pragma unroll 8
    for (int k = 0; k < 256; k++) acc = fmaf(xs[l][k], g_wcat[k * 64 + c], acc);
    g_qkn[(node0 + l) * 64 + c] = acc;
}

__global__ void k_fill_md() {
    int i = blockIdx.x * blockDim.x + threadIdx.x;
    if (i >= NN * 4) return;
    g_m[i] = -FLT_MAX;
    g_den[i] = 0.f;
}

__global__ void k_att1(const int* __restrict__ src, const int* __restrict__ dstp,
                       const int* __restrict__ et, int layer) {
    int e = blockIdx.x * blockDim.x + threadIdx.x;
    if (e >= EE) return;
    float* araw = (layer == 0) ? g_a1s : g_a2s;
    int s = clampi(src[e], 0, NN - 1);
    int d = clampi(dstp[e], 0, NN - 1);
    int r = clampi(et[e], 0, RR - 1);
    const float* qi = g_qkn + (long)d * 64 + r * 4;
    const float* kj = g_qkn + (long)s * 64 + 32 + r * 4;
#pragma unroll
    for (int h = 0; h < 4; h++) {
        float a = lrelu(qi[h] + kj[h], 0.2f);
        araw[(long)e * 4 + h] = a;
        atomicMaxF(&g_m[d * 4 + h], a);
    }
}

__global__ void k_att2(const int* __restrict__ dstp, int layer) {
    int e = blockIdx.x * blockDim.x + threadIdx.x;
    if (e >= EE) return;
    float* araw = (layer == 0) ? g_a1s : g_a2s;
    int d = clampi(dstp[e], 0, NN - 1);
#pragma unroll
    for (int h = 0; h < 4; h++) {
        float ex = expf(araw[(long)e * 4 + h] - g_m[d * 4 + h]);
        araw[(long)e * 4 + h] = ex;
        atomicAdd(&g_den[d * 4 + h], ex);
    }
}

__global__ void k_att3(const int* __restrict__ dstp, int layer) {
    int e = blockIdx.x * blockDim.x + threadIdx.x;
    if (e >= EE) return;
    float* alpha = (layer == 0) ? g_a1s : g_a2s;
    int d = clampi(dstp[e], 0, NN - 1);
#pragma unroll
    for (int h = 0; h < 4; h++)
        alpha[(long)e * 4 + h] = alpha[(long)e * 4 + h] / g_den[d * 4 + h];
}

__global__ void k_init_bias256(const float* __restrict__ b, int layer) {
    int i = blockIdx.x * blockDim.x + threadIdx.x;
    if (i >= NN * 256) return;
    float* out = (layer == 0) ? g_hmid : g_outp;
    out[i] = b[i & 255];
}

__global__ void k_msg_csr(const int* __restrict__ src, int layer, int rel) {
    int wid = (blockIdx.x * blockDim.x + threadIdx.x) >> 5;
    int lane = threadIdx.x & 31;
    if (wid >= NN) return;
    long bkt = (long)rel * NN + wid;
    int a = g_off2[bkt], b = g_off2[bkt + 1];
    if (a >= b) return;
    const float* alpha = (layer == 0) ? g_a1s : g_a2s;
    float* out = (layer == 0) ? g_hmid : g_outp;
    int hh = lane >> 3;
    float acc[8];
#pragma unroll
    for (int j = 0; j < 8; j++) acc[j] = 0.f;
    for (int i = a; i < b; i++) {
        int e = g_eord2[i];
        int s = clampi(src[e], 0, NN - 1);
        float al = alpha[(long)e * 4 + hh];
        const float4* tp = (const float4*)(g_T + (long)s * 256 + lane * 8);
        float4 v0 = tp[0], v1 = tp[1];
        acc[0] = fmaf(al, v0.x, acc[0]); acc[1] = fmaf(al, v0.y, acc[1]);
        acc[2] = fmaf(al, v0.z, acc[2]); acc[3] = fmaf(al, v0.w, acc[3]);
        acc[4] = fmaf(al, v1.x, acc[4]); acc[5] = fmaf(al, v1.y, acc[5]);
        acc[6] = fmaf(al, v1.z, acc[6]); acc[7] = fmaf(al, v1.w, acc[7]);
    }
    float4* op = (float4*)(out + (long)wid * 256 + lane * 8);
    float4 o0 = op[0], o1 = op[1];
    o0.x += acc[0]; o0.y += acc[1]; o0.z += acc[2]; o0.w += acc[3];
    o1.x += acc[4]; o1.y += acc[5]; o1.z += acc[6]; o1.w += acc[7];
    op[0] = o0; op[1] = o1;
}

__global__ void k_leaky_hmid(float s) {
    int i = blockIdx.x * blockDim.x + threadIdx.x;
    if (i >= NN * 256) return;
    g_hmid[i] = lrelu(g_hmid[i], s);
}

__global__ void k_final_bias(const float* __restrict__ lb) {
    int i = blockIdx.x * blockDim.x + threadIdx.x;
    if (i >= NN * 256) return;
    g_outp[i] += lb[i & 255];
}

__global__ void k_out(float* __restrict__ outp, long osz) {
    long i = (long)blockIdx.x * blockDim.x + threadIdx.x;
    if (i >= SZ_OUT || i >= osz) return;
    float v;
    if (i < SZ_256)             v = g_outp[i];
    else if (i < SZ_256 + SZ_A) v = g_a1s[i - SZ_256];
    else                        v = g_a2s[i - SZ_256 - SZ_A];
    outp[i] = v;
}

// ---------------- host side ----------------
extern "C" void kernel_launch(void* const* d_in, const int* in_sizes, int n_in,
                              void* d_out, int out_size) {
    int I_KG = 0, I_CC = 1, I_GW1 = 2, I_GB1 = 3, I_GW2 = 4, I_GB2 = 5;
    int I_R1W = 6, I_R1Q = 7, I_R1K = 8, I_R1B = 9;
    int I_R2W = 10, I_R2Q = 11, I_R2K = 12, I_R2B = 13;
    int I_LW = 14, I_LB = 15, I_EI = 16, I_ET = 17;
    if (n_in >= 18 && in_sizes[16] == 2 * EE && in_sizes[17] == EE) {
        // insertion order (defaults)
    } else if (n_in >= 18 && in_sizes[1] == 2 * EE && in_sizes[2] == EE) {
        I_CC = 0;  I_EI = 1;  I_ET = 2;  I_GB1 = 3; I_GB2 = 4; I_GW1 = 5; I_GW2 = 6;
        I_KG = 7;  I_LB = 8;  I_LW = 9;
        I_R1B = 10; I_R1K = 11; I_R1Q = 12; I_R1W = 13;
        I_R2B = 14; I_R2K = 15; I_R2Q = 16; I_R2W = 17;
    }

    const float* kg    = (const float*)d_in[I_KG];
    const float* ccle0 = (const float*)d_in[I_CC];
    const float* gw1   = (const float*)d_in[I_GW1];
    const float* gb1   = (const float*)d_in[I_GB1];
    const float* gw2   = (const float*)d_in[I_GW2];
    const float* gb2   = (const float*)d_in[I_GB2];
    const float* r1w   = (const float*)d_in[I_R1W];
    const float* r1q   = (const float*)d_in[I_R1Q];
    const float* r1k   = (const float*)d_in[I_R1K];
    const float* r1b   = (const float*)d_in[I_R1B];
    const float* r2w   = (const float*)d_in[I_R2W];
    const float* r2q   = (const float*)d_in[I_R2Q];
    const float* r2k   = (const float*)d_in[I_R2K];
    const float* r2b   = (const float*)d_in[I_R2B];
    const float* linw  = (const float*)d_in[I_LW];
    const float* linb  = (const float*)d_in[I_LB];
    const int*   ei    = (const int*)d_in[I_EI];
    const int*   et    = (const int*)d_in[I_ET];
    const int* src = ei;
    const int* dst = ei + EE;

    cudaFuncSetAttribute(k_hmma, cudaFuncAttributeMaxDynamicSharedMemorySize, HM_SMEM);
    dim3 hmg(157, 4, 1);

    // ---- CSR build + degree ----
    k_zero_hist<<<(RR * NN + 255) / 256, 256>>>();
    k_ehist<<<(EE + 255) / 256, 256>>>(dst, et);
    k_scanA<<<(NN + 1023) / 1024, 1024>>>(0);
    k_scanB<<<1, 256>>>((NN + 1023) / 1024);
    k_scanC<<<(NN + 1023) / 1024, 1024>>>(0);
    k_scanA<<<(RR * NN + 1023) / 1024, 1024>>>(1);
    k_scanB<<<1, 256>>>((RR * NN + 1023) / 1024);
    k_scanC<<<(RR * NN + 1023) / 1024, 1024>>>(1);
    k_pos_copy<<<(RR * NN + 255) / 256, 256>>>();
    k_escat<<<(EE + 255) / 256, 256>>>(dst, et);
    k_dis<<<(NN + 255) / 256, 256>>>();

    // ---- weight conversions (lin at slot 8, once) ----
    k_convW<<<(65536 + 255) / 256, 256>>>(linw, 1, 8);

    // ---- GCN layer 1 (4 -> 32) ----
    k_h1<<<(NN * 32 + 255) / 256, 256>>>(ccle0, gw1);
    k_gcn_init32<<<(NN * 32 + 255) / 256, 256>>>(gb1);
    k_gcn_csr1<<<(NN * 32 + 255) / 256, 256>>>(src);
    k_leaky_c1<<<(NN * 32 + 255) / 256, 256>>>(0.01f);

    // ---- GCN layer 2 (32 -> 128) ----
    k_h2<<<NN, 128>>>(gw2);
    k_build_x0<<<(NN * 256 + 255) / 256, 256>>>(kg, gb2);
    k_gcn_csr2<<<NN, 128>>>(src);

    // ---- convert x0 to bf16 split ----
    k_convA<<<(int)(((long)NPAD * 256 + 255) / 256), 256>>>(0);

    // ---- RGAT layer 1 (g_x0 -> g_hmid) ----
    k_wcat<<<256, 64>>>(r1w, r1q, r1k);
    k_mmA<<<NN / 4, 256>>>(0);
    k_fill_md<<<(NN * 4 + 255) / 256, 256>>>();
    k_att1<<<(EE + 255) / 256, 256>>>(src, dst, et, 0);
    k_att2<<<(EE + 255) / 256, 256>>>(dst, 0);
    k_att3<<<(EE + 255) / 256, 256>>>(dst, 0);
    k_init_bias256<<<(NN * 256 + 255) / 256, 256>>>(r1b, 0);
    k_convW<<<(8 * 65536 + 255) / 256, 256>>>(r1w, 8, 0);
    for (int r = 0; r < RR; r++) {
        k_hmma<<<hmg, 256, HM_SMEM>>>(0, r, 0, 0);
        k_msg_csr<<<(NN * 32 + 255) / 256, 256>>>(src, 0, r);
    }
    k_leaky_hmid<<<(NN * 256 + 255) / 256, 256>>>(0.01f);
    k_convA<<<(int)(((long)NPAD * 256 + 255) / 256), 256>>>(1);

    // ---- RGAT layer 2 (g_hmid -> g_outp) ----
    k_wcat<<<256, 64>>>(r2w, r2q, r2k);
    k_mmA<<<NN / 4, 256>>>(1);
    k_fill_md<<<(NN * 4 + 255) / 256, 256>>>();
    k_att1<<<(EE + 255) / 256, 256>>>(src, dst, et, 1);
    k_att2<<<(EE + 255) / 256, 256>>>(dst, 1);
    k_att3<<<(EE + 255) / 256, 256>>>(dst, 1);
    k_init_bias256<<<(NN * 256 + 255) / 256, 256>>>(r2b, 1);
    k_convW<<<(8 * 65536 + 255) / 256, 256>>>(r2w, 8, 0);
    for (int r = 0; r < RR; r++) {
        k_hmma<<<hmg, 256, HM_SMEM>>>(1, r, 0, 0);
        k_msg_csr<<<(NN * 32 + 255) / 256, 256>>>(src, 1, r);
    }

    // ---- residual lin: g_outp += g_x0 @ linw, + linb ----
    k_hmma<<<hmg, 256, HM_SMEM>>>(0, 8, 1, 1);
    k_final_bias<<<(NN * 256 + 255) / 256, 256>>>(linb);

    // ---- write d_out ----
    k_out<<<(int)((SZ_OUT + 255) / 256), 256>>>((float*)d_out, (long)out_size);
}

// round 17
// speedup vs baseline: 1.2193x; 1.2193x over previous
#include <cuda_runtime.h>
#include <cuda_bf16.h>
#include <cstdint>
#include <math.h>
#include <float.h>

#define NN 20000
#define EE 320000
#define RR 8
#define NPAD 20096   // 157 * 128

// ---------------- scratch (device globals) ----------------
__device__ float g_dis[NN];
__device__ float g_h1[NN * 32];
__device__ float g_c1[NN * 32];
__device__ float g_h2[NN * 128];
__device__ __align__(16) float g_x0[NN * 256];
__device__ __align__(16) float g_hmid[NN * 256];
__device__ __align__(16) float g_outp[NN * 256];
__device__ __align__(16) float g_T8[(long)RR * NN * 256];   // per-relation transforms
__device__ float g_qkn[NN * 64];
__device__ float g_m[NN * 4];
__device__ float g_den[NN * 4];
__device__ float g_wcat[256 * 64];
__device__ float g_a1s[EE * 4];   // fallback alpha storage
__device__ float g_a2s[EE * 4];

// bf16-split staging
__device__ __align__(16) __nv_bfloat16 g_Xhi[(long)NPAD * 256];
__device__ __align__(16) __nv_bfloat16 g_Xlo[(long)NPAD * 256];
__device__ __align__(16) __nv_bfloat16 g_Hhi[(long)NPAD * 256];
__device__ __align__(16) __nv_bfloat16 g_Hlo[(long)NPAD * 256];
__device__ __align__(16) __nv_bfloat16 g_Bhi[9L * 65536];   // slots 0-7 rel, 8 lin (Wt[n][k])
__device__ __align__(16) __nv_bfloat16 g_Blo[9L * 65536];

// CSR infrastructure (dst only)
__device__ int g_degi[NN];
__device__ int g_offD[NN + 1];
__device__ int g_posD[NN];
__device__ int g_eordD[EE];
__device__ int g_bsum[512];

#define SZ_256  ((long)NN * 256)
#define SZ_A    ((long)EE * 4)
#define SZ_OUT  (SZ_256 + 2 * SZ_A)

// ---------------- helpers ----------------
__device__ __forceinline__ float lrelu(float x, float s) { return x > 0.f ? x : s * x; }

__device__ __forceinline__ int clampi(int v, int lo, int hi) {
    return v < lo ? lo : (v > hi ? hi : v);
}

__device__ __forceinline__ void atomicMaxF(float* addr, float v) {
    if (v >= 0.f) atomicMax((int*)addr, __float_as_int(v));
    else          atomicMin((unsigned int*)addr, __float_as_uint(v));
}

// ---------------- CSR build (dst only) ----------------
__global__ void k_zero_hist() {
    int i = blockIdx.x * blockDim.x + threadIdx.x;
    if (i < NN) g_degi[i] = 0;
}

__global__ void k_ehist(const int* __restrict__ dstp) {
    int e = blockIdx.x * blockDim.x + threadIdx.x;
    if (e >= EE) return;
    atomicAdd(&g_degi[clampi(dstp[e], 0, NN - 1)], 1);
}

__global__ void k_scanA() {
    __shared__ int sh[1024];
    int t = threadIdx.x;
    int i = blockIdx.x * 1024 + t;
    sh[t] = (i < NN) ? g_degi[i] : 0;
    __syncthreads();
    for (int o = 512; o > 0; o >>= 1) {
        if (t < o) sh[t] += sh[t + o];
        __syncthreads();
    }
    if (t == 0) g_bsum[blockIdx.x] = sh[0];
}

__global__ void k_scanB(int nb) {
    __shared__ int sh[256];
    int t = threadIdx.x;
    int own = (t < nb) ? g_bsum[t] : 0;
    sh[t] = own;
    __syncthreads();
    for (int o = 1; o < 256; o <<= 1) {
        int v = (t >= o) ? sh[t - o] : 0;
        __syncthreads();
        sh[t] += v;
        __syncthreads();
    }
    if (t < nb) g_bsum[t] = sh[t] - own;   // exclusive
}

__global__ void k_scanC() {
    __shared__ int sh[1024];
    int t = threadIdx.x;
    int i = blockIdx.x * 1024 + t;
    int own = (i < NN) ? g_degi[i] : 0;
    sh[t] = own;
    __syncthreads();
    for (int o = 1; o < 1024; o <<= 1) {
        int v = (t >= o) ? sh[t - o] : 0;
        __syncthreads();
        sh[t] += v;
        __syncthreads();
    }
    int base = g_bsum[blockIdx.x];
    if (i < NN) {
        g_offD[i] = base + sh[t] - own;
        if (i == NN - 1) g_offD[NN] = base + sh[t];
    }
}

__global__ void k_pos_copy() {
    int i = blockIdx.x * blockDim.x + threadIdx.x;
    if (i < NN) g_posD[i] = g_offD[i];
}

__global__ void k_escat(const int* __restrict__ dstp) {
    int e = blockIdx.x * blockDim.x + threadIdx.x;
    if (e >= EE) return;
    int d = clampi(dstp[e], 0, NN - 1);
    int sD = atomicAdd(&g_posD[d], 1);
    if (sD >= 0 && sD < EE) g_eordD[sD] = e;
}

__global__ void k_dis() {
    int i = blockIdx.x * blockDim.x + threadIdx.x;
    if (i < NN) g_dis[i] = rsqrtf((float)g_degi[i] + 1.0f);
}

// ---------------- GCN ----------------
__global__ void k_h1(const float* __restrict__ x, const float* __restrict__ W) {
    int i = blockIdx.x * blockDim.x + threadIdx.x;
    if (i >= NN * 32) return;
    int n = i >> 5, j = i & 31;
    float c0 = x[n * 4 + 0], c1 = x[n * 4 + 1], c2 = x[n * 4 + 2], c3 = x[n * 4 + 3];
    g_h1[i] = c0 * W[j] + c1 * W[32 + j] + c2 * W[64 + j] + c3 * W[96 + j];
}

__global__ void k_gcn_init32(const float* __restrict__ b) {
    int i = blockIdx.x * blockDim.x + threadIdx.x;
    if (i >= NN * 32) return;
    int n = i >> 5, j = i & 31;
    float d = g_dis[n];
    g_c1[i] = b[j] + d * d * g_h1[i];
}

__global__ void k_gcn_csr1(const int* __restrict__ src) {
    int wid = (blockIdx.x * blockDim.x + threadIdx.x) >> 5;
    int lane = threadIdx.x & 31;
    if (wid >= NN) return;
    int a = g_offD[wid], b = g_offD[wid + 1];
    float acc = 0.f;
    for (int i = a; i < b; i++) {
        int e = g_eordD[i];
        int s = clampi(src[e], 0, NN - 1);
        acc = fmaf(g_dis[s], g_h1[(long)s * 32 + lane], acc);
    }
    g_c1[(long)wid * 32 + lane] += g_dis[wid] * acc;
}

__global__ void k_leaky_c1(float s) {
    int i = blockIdx.x * blockDim.x + threadIdx.x;
    if (i >= NN * 32) return;
    g_c1[i] = lrelu(g_c1[i], s);
}

__global__ void k_h2(const float* __restrict__ W2) {
    __shared__ float cs[32];
    int n = blockIdx.x, t = threadIdx.x;
    if (t < 32) cs[t] = g_c1[(long)n * 32 + t];
    __syncthreads();
    float acc = 0.f;
#pragma unroll
    for (int k = 0; k < 32; k++) acc = fmaf(cs[k], W2[k * 128 + t], acc);
    g_h2[(long)n * 128 + t] = acc;
}

__global__ void k_build_x0(const float* __restrict__ kg, const float* __restrict__ b2) {
    int i = blockIdx.x * blockDim.x + threadIdx.x;
    if (i >= NN * 256) return;
    int n = i >> 8, c = i & 255;
    if (c < 128) g_x0[i] = kg[(long)n * 128 + c];
    else {
        float d = g_dis[n];
        g_x0[i] = b2[c - 128] + d * d * g_h2[(long)n * 128 + (c - 128)];
    }
}

__global__ void k_gcn_csr2(const int* __restrict__ src) {
    int d = blockIdx.x, t = threadIdx.x;
    int a = g_offD[d], b = g_offD[d + 1];
    float acc = 0.f;
    for (int i = a; i < b; i++) {
        int e = g_eordD[i];
        int s = clampi(src[e], 0, NN - 1);
        acc = fmaf(g_dis[s], g_h2[(long)s * 128 + t], acc);
    }
    g_x0[(long)d * 256 + 128 + t] += g_dis[d] * acc;
}

// ---------------- bf16-split conversions ----------------
__global__ void k_convA0() {   // g_x0 -> g_Xhi/g_Xlo (full NPAD range)
    long i = (long)blockIdx.x * blockDim.x + threadIdx.x;
    if (i >= (long)NPAD * 256) return;
    float v = (i < SZ_256) ? g_x0[i] : 0.f;
    __nv_bfloat16 h = __float2bfloat16(v);
    g_Xhi[i] = h;
    g_Xlo[i] = __float2bfloat16(v - __bfloat162float(h));
}

// W[r][k][n] fp32 -> slot (slot0+r): Wt[n][k] bf16 hi/lo (K-major per output col)
__global__ void k_convW(const float* __restrict__ W, int nrel, int slot0) {
    long i = (long)blockIdx.x * blockDim.x + threadIdx.x;
    if (i >= (long)nrel * 65536) return;
    int r = (int)(i >> 16);
    int rem = (int)(i & 65535);
    int n = rem >> 8, k = rem & 255;
    float v = W[(long)r * 65536 + (long)k * 256 + n];
    __nv_bfloat16 h = __float2bfloat16(v);
    __nv_bfloat16 l = __float2bfloat16(v - __bfloat162float(h));
    long o = (long)(slot0 + r) * 65536 + (long)n * 256 + k;
    g_Bhi[o] = h;
    g_Blo[o] = l;
}

// ---------------- HMMA GEMM ----------------
// grid (157, 4, nrel); rel = blockIdx.z.
// cmode 0: C = g_T8 + rel*SZ_256  (B slot = slot0 + rel)
// cmode 1: C = g_outp (accum), single z.
#define HW 132
#define OFF_AH 0
#define OFF_AL (128 * HW)
#define OFF_BH (256 * HW)
#define OFF_BL (256 * HW + 64 * HW)
#define HM_SMEM ((256 * HW + 128 * HW) * 4)   // 202752 bytes

__device__ __forceinline__ void hmma(float* c, uint32_t a0, uint32_t a1, uint32_t a2,
                                     uint32_t a3, uint32_t b0, uint32_t b1) {
    asm volatile(
        "mma.sync.aligned.m16n8k16.row.col.f32.bf16.bf16.f32 "
        "{%0,%1,%2,%3}, {%4,%5,%6,%7}, {%8,%9}, {%0,%1,%2,%3};"
        : "+f"(c[0]), "+f"(c[1]), "+f"(c[2]), "+f"(c[3])
        : "r"(a0), "r"(a1), "r"(a2), "r"(a3), "r"(b0), "r"(b1));
}

__global__ __launch_bounds__(256, 1) void k_hmma(int asel, int slot0, int cmode, int accum) {
    extern __shared__ __align__(16) uint32_t sw[];
    int tid = threadIdx.x;
    int w = tid >> 5, lane = tid & 31;
    int g = lane >> 2, j = lane & 3;
    int rel = blockIdx.z;
    long m0 = (long)blockIdx.x * 128;
    long n0 = (long)blockIdx.y * 64;

    const __nv_bfloat16* Ah = asel ? g_Hhi : g_Xhi;
    const __nv_bfloat16* Al = asel ? g_Hlo : g_Xlo;
    const __nv_bfloat16* Bh = g_Bhi + (long)(slot0 + rel) * 65536;
    const __nv_bfloat16* Bl = g_Blo + (long)(slot0 + rel) * 65536;

    for (int i = tid; i < 4096; i += 256) {
        int row = i >> 5, q = i & 31;
        long srcb = (m0 + row) * 256 + q * 8;
        *(uint4*)(sw + OFF_AH + row * HW + q * 4) = *(const uint4*)(Ah + srcb);
        *(uint4*)(sw + OFF_AL + row * HW + q * 4) = *(const uint4*)(Al + srcb);
    }
    for (int i = tid; i < 2048; i += 256) {
        int row = i >> 5, q = i & 31;
        long srcb = (n0 + row) * 256 + q * 8;
        *(uint4*)(sw + OFF_BH + row * HW + q * 4) = *(const uint4*)(Bh + srcb);
        *(uint4*)(sw + OFF_BL + row * HW + q * 4) = *(const uint4*)(Bl + srcb);
    }
    __syncthreads();

    float c[8][4];
#pragma unroll
    for (int nt = 0; nt < 8; nt++)
#pragma unroll
        for (int q = 0; q < 4; q++) c[nt][q] = 0.f;

    const uint32_t* aHbase = sw + OFF_AH + (w * 16 + g) * HW;
    const uint32_t* aLbase = sw + OFF_AL + (w * 16 + g) * HW;

    for (int kc = 0; kc < 16; kc++) {
        int kw = kc * 8 + j;
        uint32_t ah0 = aHbase[kw];
        uint32_t ah1 = aHbase[8 * HW + kw];
        uint32_t ah2 = aHbase[kw + 4];
        uint32_t ah3 = aHbase[8 * HW + kw + 4];
        uint32_t al0 = aLbase[kw];
        uint32_t al1 = aLbase[8 * HW + kw];
        uint32_t al2 = aLbase[kw + 4];
        uint32_t al3 = aLbase[8 * HW + kw + 4];
#pragma unroll
        for (int nt = 0; nt < 8; nt++) {
            const uint32_t* bH = sw + OFF_BH + (nt * 8 + g) * HW;
            const uint32_t* bL = sw + OFF_BL + (nt * 8 + g) * HW;
            uint32_t bh0 = bH[kw], bh1 = bH[kw + 4];
            uint32_t bl0 = bL[kw], bl1 = bL[kw + 4];
            hmma(c[nt], ah0, ah1, ah2, ah3, bh0, bh1);
            hmma(c[nt], ah0, ah1, ah2, ah3, bl0, bl1);
            hmma(c[nt], al0, al1, al2, al3, bh0, bh1);
        }
    }

    float* C = (cmode == 0) ? (g_T8 + (long)rel * SZ_256) : g_outp;
    long r0 = m0 + w * 16 + g;
    long r1 = r0 + 8;
#pragma unroll
    for (int nt = 0; nt < 8; nt++) {
        long col = n0 + nt * 8 + 2 * j;
        if (r0 < NN) {
            float* p = C + r0 * 256 + col;
            if (accum) { p[0] += c[nt][0]; p[1] += c[nt][1]; }
            else       { p[0] = c[nt][0];  p[1] = c[nt][1]; }
        }
        if (r1 < NN) {
            float* p = C + r1 * 256 + col;
            if (accum) { p[0] += c[nt][2]; p[1] += c[nt][3]; }
            else       { p[0] = c[nt][2];  p[1] = c[nt][3]; }
        }
    }
}

// ---------------- attention ----------------
__global__ void k_wcat(const float* __restrict__ W, const float* __restrict__ q,
                       const float* __restrict__ k) {
    int i = blockIdx.x, t = threadIdx.x;
    int c = t & 31, r = c >> 2, h = c & 3;
    const float* qk = (t >= 32) ? k : q;
    const float* wp = W + (long)r * 65536 + (long)i * 256;
    float acc = 0.f;
#pragma unroll 8
    for (int j = 0; j < 256; j++) acc = fmaf(wp[j], qk[j * 4 + h], acc);
    g_wcat[i * 64 + t] = acc;
}

__global__ void k_mmA(int amode) {
    __shared__ float xs[4][256];
    const float* A = (amode == 0) ? g_x0 : g_hmid;
    int t = threadIdx.x;
    long node0 = (long)blockIdx.x * 4;
    for (int i = t; i < 1024; i += 256) xs[i >> 8][i & 255] = A[node0 * 256 + i];
    __syncthreads();
    int l = t >> 6, c = t & 63;
    float acc = 0.f;
#pragma unroll 8
    for (int k = 0; k < 256; k++) acc = fmaf(xs[l][k], g_wcat[k * 64 + c], acc);
    g_qkn[(node0 + l) * 64 + c] = acc;
}

__global__ void k_fill_md() {
    int i = blockIdx.x * blockDim.x + threadIdx.x;
    if (i >= NN * 4) return;
    g_m[i] = -FLT_MAX;
    g_den[i] = 0.f;
}

__global__ void k_att1(const int* __restrict__ src, const int* __restrict__ dstp,
                       const int* __restrict__ et, float* __restrict__ araw) {
    int e = blockIdx.x * blockDim.x + threadIdx.x;
    if (e >= EE) return;
    int s = clampi(src[e], 0, NN - 1);
    int d = clampi(dstp[e], 0, NN - 1);
    int r = clampi(et[e], 0, RR - 1);
    const float* qi = g_qkn + (long)d * 64 + r * 4;
    const float* kj = g_qkn + (long)s * 64 + 32 + r * 4;
#pragma unroll
    for (int h = 0; h < 4; h++) {
        float a = lrelu(qi[h] + kj[h], 0.2f);
        araw[(long)e * 4 + h] = a;
        atomicMaxF(&g_m[d * 4 + h], a);
    }
}

__global__ void k_att2(const int* __restrict__ dstp, float* __restrict__ araw) {
    int e = blockIdx.x * blockDim.x + threadIdx.x;
    if (e >= EE) return;
    int d = clampi(dstp[e], 0, NN - 1);
#pragma unroll
    for (int h = 0; h < 4; h++) {
        float ex = expf(araw[(long)e * 4 + h] - g_m[d * 4 + h]);
        araw[(long)e * 4 + h] = ex;
        atomicAdd(&g_den[d * 4 + h], ex);
    }
}

__global__ void k_att3(const int* __restrict__ dstp, float* __restrict__ alpha) {
    int e = blockIdx.x * blockDim.x + threadIdx.x;
    if (e >= EE) return;
    int d = clampi(dstp[e], 0, NN - 1);
#pragma unroll
    for (int h = 0; h < 4; h++)
        alpha[(long)e * 4 + h] = alpha[(long)e * 4 + h] / g_den[d * 4 + h];
}

// fused message pass: warp per dst, all relations via dst-CSR + per-edge rel.
// layer 0: out = lrelu(bias + sum) -> g_hmid (+ bf16 split into g_Hhi/g_Hlo)
// layer 1: out = bias + sum -> g_outp
__global__ void k_msg_all(const int* __restrict__ src, const int* __restrict__ et,
                          const float* __restrict__ alpha, const float* __restrict__ bias,
                          int layer) {
    int wd = (blockIdx.x * blockDim.x + threadIdx.x) >> 5;
    int lane = threadIdx.x & 31;
    if (wd >= NN) return;
    int a = g_offD[wd], b = g_offD[wd + 1];
    int col = lane * 8;
    int hh = lane >> 3;
    float acc[8];
#pragma unroll
    for (int j = 0; j < 8; j++) acc[j] = bias[col + j];
    for (int i = a; i < b; i++) {
        int e = g_eordD[i];
        int r = clampi(et[e], 0, RR - 1);
        int s = clampi(src[e], 0, NN - 1);
        float al = alpha[(long)e * 4 + hh];
        const float4* tp = (const float4*)(g_T8 + (long)r * SZ_256 + (long)s * 256 + col);
        float4 v0 = tp[0], v1 = tp[1];
        acc[0] = fmaf(al, v0.x, acc[0]); acc[1] = fmaf(al, v0.y, acc[1]);
        acc[2] = fmaf(al, v0.z, acc[2]); acc[3] = fmaf(al, v0.w, acc[3]);
        acc[4] = fmaf(al, v1.x, acc[4]); acc[5] = fmaf(al, v1.y, acc[5]);
        acc[6] = fmaf(al, v1.z, acc[6]); acc[7] = fmaf(al, v1.w, acc[7]);
    }
    long base = (long)wd * 256 + col;
    if (layer == 0) {
#pragma unroll
        for (int j = 0; j < 8; j++) {
            float v = lrelu(acc[j], 0.01f);
            g_hmid[base + j] = v;
            __nv_bfloat16 h = __float2bfloat16(v);
            g_Hhi[base + j] = h;
            g_Hlo[base + j] = __float2bfloat16(v - __bfloat162float(h));
        }
    } else {
        float4* op = (float4*)(g_outp + base);
        op[0] = make_float4(acc[0], acc[1], acc[2], acc[3]);
        op[1] = make_float4(acc[4], acc[5], acc[6], acc[7]);
    }
}

// d_out[0..SZ_256) = g_outp + linb  (tail already written by att3)
__global__ void k_final_bias(const float* __restrict__ lb, float* __restrict__ outp) {
    int i = blockIdx.x * blockDim.x + threadIdx.x;
    if (i >= NN * 256) return;
    outp[i] = g_outp[i] + lb[i & 255];
}

// ---------------- host side ----------------
extern "C" void kernel_launch(void* const* d_in, const int* in_sizes, int n_in,
                              void* d_out, int out_size) {
    int I_KG = 0, I_CC = 1, I_GW1 = 2, I_GB1 = 3, I_GW2 = 4, I_GB2 = 5;
    int I_R1W = 6, I_R1Q = 7, I_R1K = 8, I_R1B = 9;
    int I_R2W = 10, I_R2Q = 11, I_R2K = 12, I_R2B = 13;
    int I_LW = 14, I_LB = 15, I_EI = 16, I_ET = 17;
    if (n_in >= 18 && in_sizes[16] == 2 * EE && in_sizes[17] == EE) {
        // insertion order (defaults)
    } else if (n_in >= 18 && in_sizes[1] == 2 * EE && in_sizes[2] == EE) {
        I_CC = 0;  I_EI = 1;  I_ET = 2;  I_GB1 = 3; I_GB2 = 4; I_GW1 = 5; I_GW2 = 6;
        I_KG = 7;  I_LB = 8;  I_LW = 9;
        I_R1B = 10; I_R1K = 11; I_R1Q = 12; I_R1W = 13;
        I_R2B = 14; I_R2K = 15; I_R2Q = 16; I_R2W = 17;
    }

    const float* kg    = (const float*)d_in[I_KG];
    const float* ccle0 = (const float*)d_in[I_CC];
    const float* gw1   = (const float*)d_in[I_GW1];
    const float* gb1   = (const float*)d_in[I_GB1];
    const float* gw2   = (const float*)d_in[I_GW2];
    const float* gb2   = (const float*)d_in[I_GB2];
    const float* r1w   = (const float*)d_in[I_R1W];
    const float* r1q   = (const float*)d_in[I_R1Q];
    const float* r1k   = (const float*)d_in[I_R1K];
    const float* r1b   = (const float*)d_in[I_R1B];
    const float* r2w   = (const float*)d_in[I_R2W];
    const float* r2q   = (const float*)d_in[I_R2Q];
    const float* r2k   = (const float*)d_in[I_R2K];
    const float* r2b   = (const float*)d_in[I_R2B];
    const float* linw  = (const float*)d_in[I_LW];
    const float* linb  = (const float*)d_in[I_LB];
    const int*   ei    = (const int*)d_in[I_EI];
    const int*   et    = (const int*)d_in[I_ET];
    const int* src = ei;
    const int* dst = ei + EE;

    float* out = (float*)d_out;
    float* a1p;
    float* a2p;
    if ((long)out_size >= SZ_OUT) {
        a1p = out + SZ_256;
        a2p = a1p + SZ_A;
    } else {
        void* p1 = nullptr; void* p2 = nullptr;
        cudaGetSymbolAddress(&p1, g_a1s);
        cudaGetSymbolAddress(&p2, g_a2s);
        a1p = (float*)p1; a2p = (float*)p2;
    }

    cudaFuncSetAttribute(k_hmma, cudaFuncAttributeMaxDynamicSharedMemorySize, HM_SMEM);
    dim3 hmg8(157, 4, 8);
    dim3 hmg1(157, 4, 1);

    // ---- CSR build + degree ----
    k_zero_hist<<<(NN + 255) / 256, 256>>>();
    k_ehist<<<(EE + 255) / 256, 256>>>(dst);
    k_scanA<<<(NN + 1023) / 1024, 1024>>>();
    k_scanB<<<1, 256>>>((NN + 1023) / 1024);
    k_scanC<<<(NN + 1023) / 1024, 1024>>>();
    k_pos_copy<<<(NN + 255) / 256, 256>>>();
    k_escat<<<(EE + 255) / 256, 256>>>(dst);
    k_dis<<<(NN + 255) / 256, 256>>>();

    // ---- weight conversions (lin slot 8, once) ----
    k_convW<<<(65536 + 255) / 256, 256>>>(linw, 1, 8);

    // ---- GCN layer 1 (4 -> 32) ----
    k_h1<<<(NN * 32 + 255) / 256, 256>>>(ccle0, gw1);
    k_gcn_init32<<<(NN * 32 + 255) / 256, 256>>>(gb1);
    k_gcn_csr1<<<(NN * 32 + 255) / 256, 256>>>(src);
    k_leaky_c1<<<(NN * 32 + 255) / 256, 256>>>(0.01f);

    // ---- GCN layer 2 (32 -> 128) ----
    k_h2<<<NN, 128>>>(gw2);
    k_build_x0<<<(NN * 256 + 255) / 256, 256>>>(kg, gb2);
    k_gcn_csr2<<<NN, 128>>>(src);

    // ---- convert x0 to bf16 split ----
    k_convA0<<<(int)(((long)NPAD * 256 + 255) / 256), 256>>>();

    // ---- RGAT layer 1 (g_x0 -> g_hmid) ----
    k_wcat<<<256, 64>>>(r1w, r1q, r1k);
    k_mmA<<<NN / 4, 256>>>(0);
    k_fill_md<<<(NN * 4 + 255) / 256, 256>>>();
    k_att1<<<(EE + 255) / 256, 256>>>(src, dst, et, a1p);
    k_att2<<<(EE + 255) / 256, 256>>>(dst, a1p);
    k_att3<<<(EE + 255) / 256, 256>>>(dst, a1p);
    k_convW<<<(8 * 65536 + 255) / 256, 256>>>(r1w, 8, 0);
    k_hmma<<<hmg8, 256, HM_SMEM>>>(0, 0, 0, 0);
    k_msg_all<<<(NN * 32 + 255) / 256, 256>>>(src, et, a1p, r1b, 0);

    // ---- RGAT layer 2 (g_hmid -> g_outp) ----
    k_wcat<<<256, 64>>>(r2w, r2q, r2k);
    k_mmA<<<NN / 4, 256>>>(1);
    k_fill_md<<<(NN * 4 + 255) / 256, 256>>>();
    k_att1<<<(EE + 255) / 256, 256>>>(src, dst, et, a2p);
    k_att2<<<(EE + 255) / 256, 256>>>(dst, a2p);
    k_att3<<<(EE + 255) / 256, 256>>>(dst, a2p);
    k_convW<<<(8 * 65536 + 255) / 256, 256>>>(r2w, 8, 0);
    k_hmma<<<hmg8, 256, HM_SMEM>>>(1, 0, 0, 0);
    k_msg_all<<<(NN * 32 + 255) / 256, 256>>>(src, et, a2p, r2b, 1);

    // ---- residual lin: g_outp += g_x0 @ linw ----
    k_hmma<<<hmg1, 256, HM_SMEM>>>(0, 8, 1, 1);

    // ---- final: d_out = g_outp + linb ----
    k_final_bias<<<(NN * 256 + 255) / 256, 256>>>(linb, out);
}